// round 4
// baseline (speedup 1.0000x reference)
#include <cuda_runtime.h>
#include <cuda_bf16.h>
#include <cstddef>
#include <cstdint>

// Problem constants
#define BATCH   4
#define SEQ     4096
#define DMODEL  1024
#define DSTATE  16
#define DINNER  2048
#define BL      (BATCH*SEQ)          // 16384 rows
#define NCHUNK  32                   // SEQ/128 scan chunks
#define CHUNK   128

// ---------------------------------------------------------------------------
// Scratch (device globals; allocation APIs are forbidden)
// g_xc is reused: conv+silu output, then overwritten in place with gated y.
// ---------------------------------------------------------------------------
__device__ float g_xr[(size_t)BL * (2*DINNER)];   // x @ W_in (main | res)  256MB
__device__ float g_xc[(size_t)BL * DINNER];       // xc, then y (in place)  128MB
__device__ float g_bc[(size_t)BL * 32];           // [Bt | Ct] per row
__device__ float g_ys[(size_t)BL];                // scan scalar output
__device__ float g_E   [BATCH * NCHUNK * DSTATE]; // per-chunk end states
__device__ float g_init[BATCH * NCHUNK * DSTATE]; // per-chunk initial states

// ---------------------------------------------------------------------------
// TF32 tensor-core GEMM: C[M,N] = A[M,K] * B[K,N], row-major.
// 128x256 block tile, BK=16, 256 threads (8 warps as 2x4),
// warp tile 64x64, mma.m16n8k8.tf32, cp.async double buffering.
// Dynamic smem (~54 KB).
// ---------------------------------------------------------------------------
#define BM 128
#define BN 256
#define BKT 16
#define ASTR 20    // A smem row stride in floats (16 + 4 pad)
#define BSTR 264   // B smem row stride in floats (256 + 8 pad)
#define GEMM_SMEM_BYTES ((2*BM*ASTR + 2*BKT*BSTR) * 4)

__device__ __forceinline__ uint32_t f2tf(float f) {
    uint32_t r;
    asm("cvt.rna.tf32.f32 %0, %1;" : "=r"(r) : "f"(f));
    return r;
}

__device__ __forceinline__ void cpa16(float* dst_smem, const float* src_gmem) {
    uint32_t d = (uint32_t)__cvta_generic_to_shared(dst_smem);
    asm volatile("cp.async.ca.shared.global [%0], [%1], 16;" :: "r"(d), "l"(src_gmem));
}

__device__ __forceinline__ void mma_tf32(float d[4], const uint32_t a[4], const uint32_t b[2]) {
    asm volatile(
        "mma.sync.aligned.m16n8k8.row.col.f32.tf32.tf32.f32 "
        "{%0,%1,%2,%3}, {%4,%5,%6,%7}, {%8,%9}, {%0,%1,%2,%3};\n"
        : "+f"(d[0]), "+f"(d[1]), "+f"(d[2]), "+f"(d[3])
        : "r"(a[0]), "r"(a[1]), "r"(a[2]), "r"(a[3]), "r"(b[0]), "r"(b[1]));
}

__global__ __launch_bounds__(256, 1)
void tf32gemm(const float* __restrict__ A, const float* __restrict__ B,
              float* __restrict__ C, int M, int N, int K)
{
    extern __shared__ float smem[];
    float* As = smem;                       // [2][BM*ASTR]
    float* Bs = smem + 2 * BM * ASTR;       // [2][BKT*BSTR]

    const int tid  = threadIdx.x;
    const int lane = tid & 31;
    const int wid  = tid >> 5;
    const int wm   = wid >> 2;   // 0..1 (64 rows each)
    const int wn   = wid & 3;    // 0..3 (64 cols each)
    const int m0   = blockIdx.y * BM;
    const int n0   = blockIdx.x * BN;

    float acc[4][8][4];
#pragma unroll
    for (int mi = 0; mi < 4; mi++)
#pragma unroll
        for (int ni = 0; ni < 8; ni++)
#pragma unroll
            for (int r = 0; r < 4; r++) acc[mi][ni][r] = 0.f;

    const int NT = K / BKT;

    auto issue = [&](int kt, int buf) {
        const float* Ag = A + (size_t)m0 * K + kt * BKT;
        float* as = As + buf * BM * ASTR;
#pragma unroll
        for (int i = 0; i < 2; i++) {
            int idx = tid + i * 256;           // 512 float4s over 128x16
            int r = idx >> 2, kq = (idx & 3) * 4;
            cpa16(&as[r * ASTR + kq], Ag + (size_t)r * K + kq);
        }
        const float* Bg = B + (size_t)(kt * BKT) * N + n0;
        float* bs = Bs + buf * BKT * BSTR;
#pragma unroll
        for (int i = 0; i < 4; i++) {
            int idx = tid + i * 256;           // 1024 float4s over 16x256
            int kr = idx >> 6, nq = (idx & 63) * 4;
            cpa16(&bs[kr * BSTR + nq], Bg + (size_t)kr * N + nq);
        }
        asm volatile("cp.async.commit_group;");
    };

    issue(0, 0);

    for (int kt = 0; kt < NT; kt++) {
        if (kt + 1 < NT) {
            issue(kt + 1, (kt + 1) & 1);
            asm volatile("cp.async.wait_group 1;");
        } else {
            asm volatile("cp.async.wait_group 0;");
        }
        __syncthreads();

        const float* as = As + (kt & 1) * BM * ASTR;
        const float* bs = Bs + (kt & 1) * BKT * BSTR;

#pragma unroll
        for (int ks = 0; ks < BKT; ks += 8) {
            uint32_t af[4][4], bf[8][2];
            const int g = lane >> 2;     // group id
            const int t = lane & 3;      // thread-in-group
            const int ak = ks + t;
#pragma unroll
            for (int mi = 0; mi < 4; mi++) {
                int r = wm * 64 + mi * 16 + g;
                af[mi][0] = f2tf(as[r * ASTR + ak]);
                af[mi][1] = f2tf(as[(r + 8) * ASTR + ak]);
                af[mi][2] = f2tf(as[r * ASTR + ak + 4]);
                af[mi][3] = f2tf(as[(r + 8) * ASTR + ak + 4]);
            }
#pragma unroll
            for (int ni = 0; ni < 8; ni++) {
                int n = wn * 64 + ni * 8 + g;
                bf[ni][0] = f2tf(bs[ak * BSTR + n]);
                bf[ni][1] = f2tf(bs[(ak + 4) * BSTR + n]);
            }
#pragma unroll
            for (int mi = 0; mi < 4; mi++)
#pragma unroll
                for (int ni = 0; ni < 8; ni++)
                    mma_tf32(acc[mi][ni], af[mi], bf[ni]);
        }
        __syncthreads();
    }

    // Epilogue: c0 at (g, 2t), c1 (g, 2t+1), c2 (g+8, 2t), c3 (g+8, 2t+1)
    const int g = lane >> 2, t = lane & 3;
#pragma unroll
    for (int mi = 0; mi < 4; mi++) {
#pragma unroll
        for (int ni = 0; ni < 8; ni++) {
            int r = m0 + wm * 64 + mi * 16 + g;
            int c = n0 + wn * 64 + ni * 8 + t * 2;
            *(float2*)&C[(size_t)r * N + c]       = make_float2(acc[mi][ni][0], acc[mi][ni][1]);
            *(float2*)&C[(size_t)(r + 8) * N + c] = make_float2(acc[mi][ni][2], acc[mi][ni][3]);
        }
    }
}

// ---------------------------------------------------------------------------
// Depthwise conv (k=3, pad 1, along seq) + bias + SiLU on the main half of xr.
// ---------------------------------------------------------------------------
__global__ void conv_silu(const float* __restrict__ conv_w, const float* __restrict__ conv_b)
{
    size_t idx = (size_t)blockIdx.x * 256 + threadIdx.x;   // over BL*DINNER
    int c   = (int)(idx & (DINNER - 1));
    size_t row = idx >> 11;                                // /DINNER
    int l = (int)(row & (SEQ - 1));

    float w0 = conv_w[c * 3 + 0];
    float w1 = conv_w[c * 3 + 1];
    float w2 = conv_w[c * 3 + 2];

    float acc = conv_b[c];
    if (l > 0)       acc += w0 * g_xr[(row - 1) * (size_t)(2*DINNER) + c];
    acc                  += w1 * g_xr[ row      * (size_t)(2*DINNER) + c];
    if (l < SEQ - 1) acc += w2 * g_xr[(row + 1) * (size_t)(2*DINNER) + c];

    float s = acc / (1.f + expf(-acc));
    g_xc[idx] = s;
}

// ---------------------------------------------------------------------------
// Skinny GEMM: [Bt|Ct] (BL x 32) = xc (BL x 2048) * [W_B | W_C]
// ---------------------------------------------------------------------------
__global__ __launch_bounds__(256, 4)
void bc_gemm(const float* __restrict__ Wb, const float* __restrict__ Wc)
{
    __shared__ float xs[128][32];
    __shared__ float ws[32][32];

    const int row0 = blockIdx.x * 128;
    const int tid  = threadIdx.x;
    const int tx = tid & 31;   // output column (0..15 B, 16..31 C)
    const int ty = tid >> 5;   // row group (16 rows each)

    float acc[16];
#pragma unroll
    for (int r = 0; r < 16; r++) acc[r] = 0.f;

    for (int k0 = 0; k0 < DINNER; k0 += 32) {
        __syncthreads();
#pragma unroll
        for (int i = 0; i < 4; i++) {
            int lin = (tid + i * 256) * 4;
            int r = lin >> 5, c = lin & 31;
            float4 v = *(const float4*)&g_xc[(size_t)(row0 + r) * DINNER + k0 + c];
            *(float4*)&xs[r][c] = v;
        }
        {
            int lin = tid * 4;
            int kk = lin >> 5, c = lin & 31;
            float4 v;
            if (c < 16) v = *(const float4*)&Wb[(size_t)(k0 + kk) * 16 + c];
            else        v = *(const float4*)&Wc[(size_t)(k0 + kk) * 16 + (c - 16)];
            *(float4*)&ws[kk][c] = v;
        }
        __syncthreads();

#pragma unroll
        for (int kk = 0; kk < 32; kk++) {
            float w = ws[kk][tx];
#pragma unroll
            for (int r = 0; r < 16; r++)
                acc[r] += xs[ty * 16 + r][kk] * w;
        }
    }

#pragma unroll
    for (int r = 0; r < 16; r++)
        g_bc[(size_t)(row0 + ty * 16 + r) * 32 + tx] = acc[r];
}

// ---------------------------------------------------------------------------
// Chunked scan: phase A (chunk end-states from 0), combine, phase C (replay).
// ---------------------------------------------------------------------------
__global__ void scan_phaseA(const float* __restrict__ A)
{
    __shared__ float bcs[CHUNK][32];
    const int b = blockIdx.x >> 5;       // batch
    const int c = blockIdx.x & 31;       // chunk
    const int tid = threadIdx.x;         // 128

    const size_t base = (size_t)b * SEQ + (size_t)c * CHUNK;
    const size_t grow = (base + tid) * 32;
#pragma unroll
    for (int i = 0; i < 8; i++)
        *(float4*)&bcs[tid][i * 4] = *(const float4*)&g_bc[grow + i * 4];
    __syncthreads();

    if (tid < DSTATE) {
        float dec = 1.f / (1.f + expf(A[tid]));
        float st = 0.f;
        for (int l = 0; l < CHUNK; l++)
            st = fmaf(st, dec, bcs[l][tid]);
        g_E[(b * NCHUNK + c) * DSTATE + tid] = st;
    }
}

__global__ void scan_combine(const float* __restrict__ A)
{
    const int b = blockIdx.x;            // BATCH blocks, 16 threads
    const int s = threadIdx.x;
    float dec  = 1.f / (1.f + expf(A[s]));
    float d128 = powf(dec, (float)CHUNK);
    float S = 0.f;
    for (int c = 0; c < NCHUNK; c++) {
        g_init[(b * NCHUNK + c) * DSTATE + s] = S;
        S = S * d128 + g_E[(b * NCHUNK + c) * DSTATE + s];
    }
}

__global__ void scan_phaseC(const float* __restrict__ A)
{
    __shared__ float bcs[CHUNK][32];
    const int b = blockIdx.x >> 5;
    const int c = blockIdx.x & 31;
    const int tid = threadIdx.x;

    const size_t base = (size_t)b * SEQ + (size_t)c * CHUNK;
    const size_t grow = (base + tid) * 32;
#pragma unroll
    for (int i = 0; i < 8; i++)
        *(float4*)&bcs[tid][i * 4] = *(const float4*)&g_bc[grow + i * 4];
    __syncthreads();

    if (tid < DSTATE) {
        float dec = 1.f / (1.f + expf(A[tid]));
        float st = g_init[(b * NCHUNK + c) * DSTATE + tid];
        for (int l = 0; l < CHUNK; l++) {
            st = fmaf(st, dec, bcs[l][tid]);
            float v = st * bcs[l][16 + tid];
#pragma unroll
            for (int m = 8; m >= 1; m >>= 1)
                v += __shfl_xor_sync(0x0000ffffu, v, m, 16);
            if (tid == 0) g_ys[base + l] = v;
        }
    }
}

// ---------------------------------------------------------------------------
// Gating elementwise, IN PLACE on g_xc: xc <- (ys + xc*D) * silu(res)
// ---------------------------------------------------------------------------
__global__ void gate_y(const float* __restrict__ Dv)
{
    size_t idx = (size_t)blockIdx.x * 256 + threadIdx.x;   // over BL*DINNER
    int c = (int)(idx & (DINNER - 1));
    size_t row = idx >> 11;

    float xc  = g_xc[idx];
    float ysv = g_ys[row];
    float res = g_xr[row * (size_t)(2*DINNER) + DINNER + c];
    float sr  = res / (1.f + expf(-res));
    g_xc[idx] = (ysv + xc * Dv[c]) * sr;
}

// ---------------------------------------------------------------------------
// Launch
// ---------------------------------------------------------------------------
extern "C" void kernel_launch(void* const* d_in, const int* in_sizes, int n_in,
                              void* d_out, int out_size)
{
    const float* x      = (const float*)d_in[0];
    const float* W_in   = (const float*)d_in[1];
    const float* conv_w = (const float*)d_in[2];
    const float* conv_b = (const float*)d_in[3];
    const float* W_B    = (const float*)d_in[4];
    const float* W_C    = (const float*)d_in[5];
    const float* A      = (const float*)d_in[6];
    const float* Dv     = (const float*)d_in[7];
    const float* W_out  = (const float*)d_in[8];
    float* out = (float*)d_out;

    float *xr_p, *xc_p;
    cudaGetSymbolAddress((void**)&xr_p, g_xr);
    cudaGetSymbolAddress((void**)&xc_p, g_xc);

    cudaFuncSetAttribute(tf32gemm, cudaFuncAttributeMaxDynamicSharedMemorySize,
                         GEMM_SMEM_BYTES);

    // 1) xr = x @ W_in   (16384 x 4096, K=1024)  [TF32 tensor cores]
    {
        dim3 grid((2*DINNER) / BN, BL / BM);
        tf32gemm<<<grid, 256, GEMM_SMEM_BYTES>>>(x, W_in, xr_p, BL, 2*DINNER, DMODEL);
    }
    // 2) depthwise conv + bias + silu -> xc
    conv_silu<<<(BL * (size_t)DINNER) / 256, 256>>>(conv_w, conv_b);
    // 3) [Bt|Ct] = xc @ [W_B|W_C]
    bc_gemm<<<BL / 128, 256>>>(W_B, W_C);
    // 4) chunked scan -> ys
    scan_phaseA<<<BATCH * NCHUNK, CHUNK>>>(A);
    scan_combine<<<BATCH, DSTATE>>>(A);
    scan_phaseC<<<BATCH * NCHUNK, CHUNK>>>(A);
    // 5) gating elementwise, in place -> g_xc now holds y
    gate_y<<<(BL * (size_t)DINNER) / 256, 256>>>(Dv);
    // 6) out = y @ W_out  (16384 x 1024, K=2048)  [TF32 tensor cores]
    {
        dim3 grid(DMODEL / BN, BL / BM);
        tf32gemm<<<grid, 256, GEMM_SMEM_BYTES>>>(xc_p, W_out, out, BL, DMODEL, DINNER);
    }
}

// round 8
// speedup vs baseline: 1.1223x; 1.1223x over previous
#include <cuda_runtime.h>
#include <cuda_fp16.h>
#include <cstddef>
#include <cstdint>

// Problem constants
#define BATCH   4
#define SEQ     4096
#define DMODEL  1024
#define DSTATE  16
#define DINNER  2048
#define BL      (BATCH*SEQ)          // 16384 rows
#define NCHUNK  32                   // SEQ/128 scan chunks
#define CHUNK   128

// ---------------------------------------------------------------------------
// Scratch (device globals; allocation APIs are forbidden)
// ---------------------------------------------------------------------------
__device__ float g_xr[(size_t)BL * (2*DINNER)];   // x @ W_in (main | res)
__device__ float g_xc[(size_t)BL * DINNER];       // xc, then gated y in place
__device__ float g_bc[(size_t)BL * 32];           // [Bt | Ct] per row
__device__ float g_ys[(size_t)BL];                // scan scalar output
__device__ float g_E   [BATCH * NCHUNK * DSTATE];
__device__ float g_init[BATCH * NCHUNK * DSTATE];

// ===========================================================================
// FP16 tensor-core GEMM: C[M,N] = A[M,K] * B[K,N] (row-major fp32 I/O).
// Inputs converted to fp16 at staging (11-bit mantissa == TF32 accuracy),
// fp32 accumulate. 128x128 block tile, BK=32, 256 threads (8 warps 2x4),
// warp tile 64x32, mma.sync.m16n8k16.f16 (2x TF32 rate), double-buffered
// smem with reg-staged software pipeline.
// ===========================================================================
#define HBK   32
#define ASTRH 40     // A smem row stride in halves (32 + 8 pad)
#define BSTRH 136    // B smem row stride in halves (128 + 8 pad)

__device__ __forceinline__ uint32_t pkh(float a, float b) {
    __half2 h = __floats2half2_rn(a, b);
    return reinterpret_cast<uint32_t&>(h);
}

__device__ __forceinline__ void mma_f16(float d[4], const uint32_t a[4], const uint32_t b[2]) {
    asm volatile(
        "mma.sync.aligned.m16n8k16.row.col.f32.f16.f16.f32 "
        "{%0,%1,%2,%3}, {%4,%5,%6,%7}, {%8,%9}, {%0,%1,%2,%3};\n"
        : "+f"(d[0]), "+f"(d[1]), "+f"(d[2]), "+f"(d[3])
        : "r"(a[0]), "r"(a[1]), "r"(a[2]), "r"(a[3]), "r"(b[0]), "r"(b[1]));
}

__global__ __launch_bounds__(256)
void h16gemm(const float* __restrict__ A, const float* __restrict__ B,
             float* __restrict__ C, int M, int N, int K)
{
    __shared__ __align__(16) __half Asm[2][128 * ASTRH];
    __shared__ __align__(16) __half Bsm[2][HBK * BSTRH];

    const int tid  = threadIdx.x;
    const int lane = tid & 31;
    const int wid  = tid >> 5;
    const int wm   = wid >> 2;   // 0..1 (64 rows)
    const int wn   = wid & 3;    // 0..3 (32 cols)
    const int m0   = blockIdx.y * 128;
    const int n0   = blockIdx.x * 128;
    const int g    = lane >> 2;  // 0..7
    const int t    = lane & 3;   // 0..3

    float acc[4][4][4];
#pragma unroll
    for (int mi = 0; mi < 4; mi++)
#pragma unroll
        for (int ni = 0; ni < 4; ni++)
#pragma unroll
            for (int r = 0; r < 4; r++) acc[mi][ni][r] = 0.f;

    const int NT = K / HBK;
    float4 ar[4], br[4];

    // gmem tile -> registers
    auto ldg = [&](int kt) {
        const float* Ag = A + (size_t)m0 * K + kt * HBK;
#pragma unroll
        for (int i = 0; i < 4; i++) {
            int idx = tid + i * 256;           // 1024 float4s over 128x32
            int r = idx >> 3, c4 = (idx & 7) * 4;
            ar[i] = *(const float4*)&Ag[(size_t)r * K + c4];
        }
        const float* Bg = B + (size_t)(kt * HBK) * N + n0;
#pragma unroll
        for (int i = 0; i < 4; i++) {
            int idx = tid + i * 256;           // 1024 float4s over 32x128
            int kr = idx >> 5, nq = (idx & 31) * 4;
            br[i] = *(const float4*)&Bg[(size_t)kr * N + nq];
        }
    };

    // registers -> smem (fp32 -> fp16)
    auto sts = [&](int buf) {
#pragma unroll
        for (int i = 0; i < 4; i++) {
            int idx = tid + i * 256;
            int r = idx >> 3, c4 = (idx & 7) * 4;
            uint2 u = make_uint2(pkh(ar[i].x, ar[i].y), pkh(ar[i].z, ar[i].w));
            *(uint2*)&Asm[buf][r * ASTRH + c4] = u;
        }
#pragma unroll
        for (int i = 0; i < 4; i++) {
            int idx = tid + i * 256;
            int kr = idx >> 5, nq = (idx & 31) * 4;
            uint2 u = make_uint2(pkh(br[i].x, br[i].y), pkh(br[i].z, br[i].w));
            *(uint2*)&Bsm[buf][kr * BSTRH + nq] = u;
        }
    };

    ldg(0); sts(0);
    __syncthreads();

    for (int kt = 0; kt < NT; kt++) {
        if (kt + 1 < NT) ldg(kt + 1);    // LDG latency hidden behind mma below

        const __half* as = Asm[kt & 1];
        const __half* bs = Bsm[kt & 1];

#pragma unroll
        for (int ks = 0; ks < 2; ks++) { // two k16 steps per BK=32
            uint32_t af[4][4], bf[4][2];
            const int kh = ks * 16;
#pragma unroll
            for (int mi = 0; mi < 4; mi++) {
                int row = wm * 64 + mi * 16 + g;
                af[mi][0] = *(const uint32_t*)&as[row * ASTRH + kh + 2 * t];
                af[mi][1] = *(const uint32_t*)&as[(row + 8) * ASTRH + kh + 2 * t];
                af[mi][2] = *(const uint32_t*)&as[row * ASTRH + kh + 8 + 2 * t];
                af[mi][3] = *(const uint32_t*)&as[(row + 8) * ASTRH + kh + 8 + 2 * t];
            }
#pragma unroll
            for (int ni = 0; ni < 4; ni++) {
                int n = wn * 32 + ni * 8 + g;
                bf[ni][0] = *(const uint32_t*)&bs[n * 0 + 0];  // placeholder (overwritten)
                bf[ni][0] = *(const uint32_t*)&Bsm[kt & 1][0]; // (kept simple below)
                bf[ni][0] = *(const uint32_t*)&bs[(kh + 2 * t) * BSTRH + n];
                bf[ni][1] = *(const uint32_t*)&bs[(kh + 8 + 2 * t) * BSTRH + n];
            }
            // NOTE: B stored [k][n]; fragment needs (k=2t,2t+1 ; n=g) pairs,
            // i.e. two halves NON-contiguous in k. Load as two 16-bit each:
#pragma unroll
            for (int ni = 0; ni < 4; ni++) {
                int n = wn * 32 + ni * 8 + g;
                uint16_t l0 = *(const uint16_t*)&bs[(kh + 2 * t)     * BSTRH + n];
                uint16_t h0 = *(const uint16_t*)&bs[(kh + 2 * t + 1) * BSTRH + n];
                uint16_t l1 = *(const uint16_t*)&bs[(kh + 8 + 2 * t)     * BSTRH + n];
                uint16_t h1 = *(const uint16_t*)&bs[(kh + 8 + 2 * t + 1) * BSTRH + n];
                bf[ni][0] = (uint32_t)l0 | ((uint32_t)h0 << 16);
                bf[ni][1] = (uint32_t)l1 | ((uint32_t)h1 << 16);
            }
#pragma unroll
            for (int mi = 0; mi < 4; mi++)
#pragma unroll
                for (int ni = 0; ni < 4; ni++)
                    mma_f16(acc[mi][ni], af[mi], bf[ni]);
        }

        if (kt + 1 < NT) sts((kt + 1) & 1);
        __syncthreads();
    }

    // Epilogue: c0 (g,2t), c1 (g,2t+1), c2 (g+8,2t), c3 (g+8,2t+1)
#pragma unroll
    for (int mi = 0; mi < 4; mi++) {
#pragma unroll
        for (int ni = 0; ni < 4; ni++) {
            int r = m0 + wm * 64 + mi * 16 + g;
            int c = n0 + wn * 32 + ni * 8 + t * 2;
            *(float2*)&C[(size_t)r * N + c]       = make_float2(acc[mi][ni][0], acc[mi][ni][1]);
            *(float2*)&C[(size_t)(r + 8) * N + c] = make_float2(acc[mi][ni][2], acc[mi][ni][3]);
        }
    }
}

// ---------------------------------------------------------------------------
// Depthwise conv (k=3, pad 1, along seq) + bias + SiLU on the main half of xr.
// ---------------------------------------------------------------------------
__global__ void conv_silu(const float* __restrict__ conv_w, const float* __restrict__ conv_b)
{
    size_t idx = (size_t)blockIdx.x * 256 + threadIdx.x;   // over BL*DINNER
    int c   = (int)(idx & (DINNER - 1));
    size_t row = idx >> 11;                                // /DINNER
    int l = (int)(row & (SEQ - 1));

    float w0 = conv_w[c * 3 + 0];
    float w1 = conv_w[c * 3 + 1];
    float w2 = conv_w[c * 3 + 2];

    float acc = conv_b[c];
    if (l > 0)       acc += w0 * g_xr[(row - 1) * (size_t)(2*DINNER) + c];
    acc                  += w1 * g_xr[ row      * (size_t)(2*DINNER) + c];
    if (l < SEQ - 1) acc += w2 * g_xr[(row + 1) * (size_t)(2*DINNER) + c];

    float s = acc / (1.f + expf(-acc));
    g_xc[idx] = s;
}

// ---------------------------------------------------------------------------
// Skinny GEMM: [Bt|Ct] (BL x 32) = xc (BL x 2048) * [W_B | W_C]
// ---------------------------------------------------------------------------
__global__ __launch_bounds__(256, 4)
void bc_gemm(const float* __restrict__ Wb, const float* __restrict__ Wc)
{
    __shared__ float xs[128][32];
    __shared__ float ws[32][32];

    const int row0 = blockIdx.x * 128;
    const int tid  = threadIdx.x;
    const int tx = tid & 31;
    const int ty = tid >> 5;

    float acc[16];
#pragma unroll
    for (int r = 0; r < 16; r++) acc[r] = 0.f;

    for (int k0 = 0; k0 < DINNER; k0 += 32) {
        __syncthreads();
#pragma unroll
        for (int i = 0; i < 4; i++) {
            int lin = (tid + i * 256) * 4;
            int r = lin >> 5, c = lin & 31;
            float4 v = *(const float4*)&g_xc[(size_t)(row0 + r) * DINNER + k0 + c];
            *(float4*)&xs[r][c] = v;
        }
        {
            int lin = tid * 4;
            int kk = lin >> 5, c = lin & 31;
            float4 v;
            if (c < 16) v = *(const float4*)&Wb[(size_t)(k0 + kk) * 16 + c];
            else        v = *(const float4*)&Wc[(size_t)(k0 + kk) * 16 + (c - 16)];
            *(float4*)&ws[kk][c] = v;
        }
        __syncthreads();

#pragma unroll
        for (int kk = 0; kk < 32; kk++) {
            float w = ws[kk][tx];
#pragma unroll
            for (int r = 0; r < 16; r++)
                acc[r] += xs[ty * 16 + r][kk] * w;
        }
    }

#pragma unroll
    for (int r = 0; r < 16; r++)
        g_bc[(size_t)(row0 + ty * 16 + r) * 32 + tx] = acc[r];
}

// ---------------------------------------------------------------------------
// Chunked scan: phase A (chunk end-states from 0), combine, phase C (replay).
// ---------------------------------------------------------------------------
__global__ void scan_phaseA(const float* __restrict__ A)
{
    __shared__ float bcs[CHUNK][32];
    const int b = blockIdx.x >> 5;
    const int c = blockIdx.x & 31;
    const int tid = threadIdx.x;

    const size_t base = (size_t)b * SEQ + (size_t)c * CHUNK;
    const size_t grow = (base + tid) * 32;
#pragma unroll
    for (int i = 0; i < 8; i++)
        *(float4*)&bcs[tid][i * 4] = *(const float4*)&g_bc[grow + i * 4];
    __syncthreads();

    if (tid < DSTATE) {
        float dec = 1.f / (1.f + expf(A[tid]));
        float st = 0.f;
        for (int l = 0; l < CHUNK; l++)
            st = fmaf(st, dec, bcs[l][tid]);
        g_E[(b * NCHUNK + c) * DSTATE + tid] = st;
    }
}

__global__ void scan_combine(const float* __restrict__ A)
{
    const int b = blockIdx.x;
    const int s = threadIdx.x;
    float dec  = 1.f / (1.f + expf(A[s]));
    float d128 = powf(dec, (float)CHUNK);
    float S = 0.f;
    for (int c = 0; c < NCHUNK; c++) {
        g_init[(b * NCHUNK + c) * DSTATE + s] = S;
        S = S * d128 + g_E[(b * NCHUNK + c) * DSTATE + s];
    }
}

__global__ void scan_phaseC(const float* __restrict__ A)
{
    __shared__ float bcs[CHUNK][32];
    const int b = blockIdx.x >> 5;
    const int c = blockIdx.x & 31;
    const int tid = threadIdx.x;

    const size_t base = (size_t)b * SEQ + (size_t)c * CHUNK;
    const size_t grow = (base + tid) * 32;
#pragma unroll
    for (int i = 0; i < 8; i++)
        *(float4*)&bcs[tid][i * 4] = *(const float4*)&g_bc[grow + i * 4];
    __syncthreads();

    if (tid < DSTATE) {
        float dec = 1.f / (1.f + expf(A[tid]));
        float st = g_init[(b * NCHUNK + c) * DSTATE + tid];
        for (int l = 0; l < CHUNK; l++) {
            st = fmaf(st, dec, bcs[l][tid]);
            float v = st * bcs[l][16 + tid];
#pragma unroll
            for (int m = 8; m >= 1; m >>= 1)
                v += __shfl_xor_sync(0x0000ffffu, v, m, 16);
            if (tid == 0) g_ys[base + l] = v;
        }
    }
}

// ---------------------------------------------------------------------------
// Gating elementwise, IN PLACE on g_xc: xc <- (ys + xc*D) * silu(res)
// ---------------------------------------------------------------------------
__global__ void gate_y(const float* __restrict__ Dv)
{
    size_t idx = (size_t)blockIdx.x * 256 + threadIdx.x;
    int c = (int)(idx & (DINNER - 1));
    size_t row = idx >> 11;

    float xc  = g_xc[idx];
    float ysv = g_ys[row];
    float res = g_xr[row * (size_t)(2*DINNER) + DINNER + c];
    float sr  = res / (1.f + expf(-res));
    g_xc[idx] = (ysv + xc * Dv[c]) * sr;
}

// ---------------------------------------------------------------------------
// Launch
// ---------------------------------------------------------------------------
extern "C" void kernel_launch(void* const* d_in, const int* in_sizes, int n_in,
                              void* d_out, int out_size)
{
    const float* x      = (const float*)d_in[0];
    const float* W_in   = (const float*)d_in[1];
    const float* conv_w = (const float*)d_in[2];
    const float* conv_b = (const float*)d_in[3];
    const float* W_B    = (const float*)d_in[4];
    const float* W_C    = (const float*)d_in[5];
    const float* A      = (const float*)d_in[6];
    const float* Dv     = (const float*)d_in[7];
    const float* W_out  = (const float*)d_in[8];
    float* out = (float*)d_out;

    float *xr_p, *xc_p;
    cudaGetSymbolAddress((void**)&xr_p, g_xr);
    cudaGetSymbolAddress((void**)&xc_p, g_xc);

    // 1) xr = x @ W_in  (16384 x 4096, K=1024)  [fp16 mma, fp32 accum]
    {
        dim3 grid((2*DINNER) / 128, BL / 128);
        h16gemm<<<grid, 256>>>(x, W_in, xr_p, BL, 2*DINNER, DMODEL);
    }
    // 2) depthwise conv + bias + silu -> xc
    conv_silu<<<(BL * (size_t)DINNER) / 256, 256>>>(conv_w, conv_b);
    // 3) [Bt|Ct] = xc @ [W_B|W_C]
    bc_gemm<<<BL / 128, 256>>>(W_B, W_C);
    // 4) chunked scan -> ys
    scan_phaseA<<<BATCH * NCHUNK, CHUNK>>>(A);
    scan_combine<<<BATCH, DSTATE>>>(A);
    scan_phaseC<<<BATCH * NCHUNK, CHUNK>>>(A);
    // 5) gating elementwise, in place -> g_xc now holds y
    gate_y<<<(BL * (size_t)DINNER) / 256, 256>>>(Dv);
    // 6) out = y @ W_out  (16384 x 1024, K=2048)  [fp16 mma, fp32 accum]
    {
        dim3 grid(DMODEL / 128, BL / 128);
        h16gemm<<<grid, 256>>>(xc_p, W_out, out, BL, DMODEL, DINNER);
    }
}

// round 9
// speedup vs baseline: 1.1853x; 1.0561x over previous
#include <cuda_runtime.h>
#include <cuda_fp16.h>
#include <cstddef>
#include <cstdint>

// Problem constants
#define BATCH   4
#define SEQ     4096
#define DMODEL  1024
#define DSTATE  16
#define DINNER  2048
#define BL      (BATCH*SEQ)          // 16384 rows
#define NCHUNK  32                   // SEQ/128 scan chunks
#define CHUNK   128

// ---------------------------------------------------------------------------
// Scratch (device globals; allocation APIs are forbidden)
// ---------------------------------------------------------------------------
__device__ float g_xr[(size_t)BL * (2*DINNER)];   // x @ W_in (main | res)
__device__ float g_xc[(size_t)BL * DINNER];       // xc, then gated y in place
__device__ float g_bc[(size_t)BL * 32];           // [Bt | Ct] per row
__device__ float g_ys[(size_t)BL];                // scan scalar output
__device__ float g_E   [BATCH * NCHUNK * DSTATE];
__device__ float g_init[BATCH * NCHUNK * DSTATE];

// ===========================================================================
// FP16 tensor-core GEMM with ldmatrix fragment loads.
// C[M,N] = A[M,K] * B[K,N], fp32 I/O, fp16 operands (11-bit mantissa ==
// TF32 accuracy), fp32 accumulate. 128x128 block tile, BK=32, 256 threads
// (8 warps 2x4), warp tile 64x32, mma.sync.m16n8k16, double-buffered smem,
// reg-staged gmem pipeline.
// ===========================================================================
#define HBK   32
#define ASTRH 40     // A smem row stride in halves (32 + 8 pad)
#define BSTRH 136    // B smem row stride in halves (128 + 8 pad)

__device__ __forceinline__ uint32_t pkh(float a, float b) {
    __half2 h = __floats2half2_rn(a, b);
    return reinterpret_cast<uint32_t&>(h);
}

__device__ __forceinline__ uint32_t smem_u32(const void* p) {
    uint32_t a;
    asm("{ .reg .u64 t; cvta.to.shared.u64 t, %1; cvt.u32.u64 %0, t; }"
        : "=r"(a) : "l"(p));
    return a;
}

__device__ __forceinline__ void ldsm_x4(uint32_t r[4], uint32_t addr) {
    asm volatile("ldmatrix.sync.aligned.m8n8.x4.shared.b16 {%0,%1,%2,%3}, [%4];"
        : "=r"(r[0]), "=r"(r[1]), "=r"(r[2]), "=r"(r[3]) : "r"(addr));
}
__device__ __forceinline__ void ldsm_x4t(uint32_t r[4], uint32_t addr) {
    asm volatile("ldmatrix.sync.aligned.m8n8.x4.trans.shared.b16 {%0,%1,%2,%3}, [%4];"
        : "=r"(r[0]), "=r"(r[1]), "=r"(r[2]), "=r"(r[3]) : "r"(addr));
}

__device__ __forceinline__ void mma_f16(float d[4], const uint32_t a[4], const uint32_t b0, const uint32_t b1) {
    asm volatile(
        "mma.sync.aligned.m16n8k16.row.col.f32.f16.f16.f32 "
        "{%0,%1,%2,%3}, {%4,%5,%6,%7}, {%8,%9}, {%0,%1,%2,%3};\n"
        : "+f"(d[0]), "+f"(d[1]), "+f"(d[2]), "+f"(d[3])
        : "r"(a[0]), "r"(a[1]), "r"(a[2]), "r"(a[3]), "r"(b0), "r"(b1));
}

__global__ __launch_bounds__(256)
void h16gemm(const float* __restrict__ A, const float* __restrict__ B,
             float* __restrict__ C, int M, int N, int K)
{
    __shared__ __align__(16) __half Asm[2][128 * ASTRH];
    __shared__ __align__(16) __half Bsm[2][HBK * BSTRH];

    const int tid  = threadIdx.x;
    const int lane = tid & 31;
    const int wid  = tid >> 5;
    const int wm   = wid >> 2;   // 0..1 (64 rows)
    const int wn   = wid & 3;    // 0..3 (32 cols)
    const int m0   = blockIdx.y * 128;
    const int n0   = blockIdx.x * 128;
    const int g    = lane >> 2;  // 0..7
    const int t    = lane & 3;   // 0..3
    const int grp  = lane >> 3;  // 0..3 (ldmatrix group)
    const int wi   = lane & 7;   // row within group

    float acc[4][4][4];
#pragma unroll
    for (int mi = 0; mi < 4; mi++)
#pragma unroll
        for (int ni = 0; ni < 4; ni++)
#pragma unroll
            for (int r = 0; r < 4; r++) acc[mi][ni][r] = 0.f;

    const int NT = K / HBK;
    float4 ar[4], br[4];

    // gmem tile -> registers
    auto ldg = [&](int kt) {
        const float* Ag = A + (size_t)m0 * K + kt * HBK;
#pragma unroll
        for (int i = 0; i < 4; i++) {
            int idx = tid + i * 256;           // 1024 float4s over 128x32
            int r = idx >> 3, c4 = (idx & 7) * 4;
            ar[i] = *(const float4*)&Ag[(size_t)r * K + c4];
        }
        const float* Bg = B + (size_t)(kt * HBK) * N + n0;
#pragma unroll
        for (int i = 0; i < 4; i++) {
            int idx = tid + i * 256;           // 1024 float4s over 32x128
            int kr = idx >> 5, nq = (idx & 31) * 4;
            br[i] = *(const float4*)&Bg[(size_t)kr * N + nq];
        }
    };

    // registers -> smem (fp32 -> fp16)
    auto sts = [&](int buf) {
#pragma unroll
        for (int i = 0; i < 4; i++) {
            int idx = tid + i * 256;
            int r = idx >> 3, c4 = (idx & 7) * 4;
            uint2 u = make_uint2(pkh(ar[i].x, ar[i].y), pkh(ar[i].z, ar[i].w));
            *(uint2*)&Asm[buf][r * ASTRH + c4] = u;
        }
#pragma unroll
        for (int i = 0; i < 4; i++) {
            int idx = tid + i * 256;
            int kr = idx >> 5, nq = (idx & 31) * 4;
            uint2 u = make_uint2(pkh(br[i].x, br[i].y), pkh(br[i].z, br[i].w));
            *(uint2*)&Bsm[buf][kr * BSTRH + nq] = u;
        }
    };

    ldg(0); sts(0);
    __syncthreads();

    for (int kt = 0; kt < NT; kt++) {
        if (kt + 1 < NT) ldg(kt + 1);    // LDG latency hidden behind mma below

        const uint32_t asB = smem_u32(&Asm[kt & 1][0]);
        const uint32_t bsB = smem_u32(&Bsm[kt & 1][0]);

#pragma unroll
        for (int ks = 0; ks < 2; ks++) { // two k16 steps per BK=32
            const int kh = ks * 16;
            uint32_t af[4][4], bq[2][4];

            // A fragments: 4x ldmatrix.x4 over 16x16 tiles (row-major)
#pragma unroll
            for (int mi = 0; mi < 4; mi++) {
                int row  = wm * 64 + mi * 16 + (grp & 1) * 8 + wi;
                int colh = kh + (grp >> 1) * 8;
                ldsm_x4(af[mi], asB + (uint32_t)(row * ASTRH + colh) * 2);
            }
            // B fragments: 2x ldmatrix.x4.trans over k16 x n16 tiles
#pragma unroll
            for (int p = 0; p < 2; p++) {
                int krow = kh + (grp & 1) * 8 + wi;
                int ncol = wn * 32 + p * 16 + (grp >> 1) * 8;
                ldsm_x4t(bq[p], bsB + (uint32_t)(krow * BSTRH + ncol) * 2);
            }
            // ni 0: bq[0][0..1], ni 1: bq[0][2..3], ni 2: bq[1][0..1], ni 3: bq[1][2..3]
#pragma unroll
            for (int mi = 0; mi < 4; mi++) {
                mma_f16(acc[mi][0], af[mi], bq[0][0], bq[0][1]);
                mma_f16(acc[mi][1], af[mi], bq[0][2], bq[0][3]);
                mma_f16(acc[mi][2], af[mi], bq[1][0], bq[1][1]);
                mma_f16(acc[mi][3], af[mi], bq[1][2], bq[1][3]);
            }
        }

        if (kt + 1 < NT) sts((kt + 1) & 1);
        __syncthreads();
    }

    // Epilogue: c0 (g,2t), c1 (g,2t+1), c2 (g+8,2t), c3 (g+8,2t+1)
#pragma unroll
    for (int mi = 0; mi < 4; mi++) {
#pragma unroll
        for (int ni = 0; ni < 4; ni++) {
            int r = m0 + wm * 64 + mi * 16 + g;
            int c = n0 + wn * 32 + ni * 8 + t * 2;
            *(float2*)&C[(size_t)r * N + c]       = make_float2(acc[mi][ni][0], acc[mi][ni][1]);
            *(float2*)&C[(size_t)(r + 8) * N + c] = make_float2(acc[mi][ni][2], acc[mi][ni][3]);
        }
    }
}

// ---------------------------------------------------------------------------
// Depthwise conv (k=3, pad 1, along seq) + bias + SiLU on the main half of xr.
// ---------------------------------------------------------------------------
__global__ void conv_silu(const float* __restrict__ conv_w, const float* __restrict__ conv_b)
{
    size_t idx = (size_t)blockIdx.x * 256 + threadIdx.x;   // over BL*DINNER
    int c   = (int)(idx & (DINNER - 1));
    size_t row = idx >> 11;                                // /DINNER
    int l = (int)(row & (SEQ - 1));

    float w0 = conv_w[c * 3 + 0];
    float w1 = conv_w[c * 3 + 1];
    float w2 = conv_w[c * 3 + 2];

    float acc = conv_b[c];
    if (l > 0)       acc += w0 * g_xr[(row - 1) * (size_t)(2*DINNER) + c];
    acc                  += w1 * g_xr[ row      * (size_t)(2*DINNER) + c];
    if (l < SEQ - 1) acc += w2 * g_xr[(row + 1) * (size_t)(2*DINNER) + c];

    float s = acc / (1.f + expf(-acc));
    g_xc[idx] = s;
}

// ---------------------------------------------------------------------------
// Skinny GEMM: [Bt|Ct] (BL x 32) = xc (BL x 2048) * [W_B | W_C]
// ---------------------------------------------------------------------------
__global__ __launch_bounds__(256, 4)
void bc_gemm(const float* __restrict__ Wb, const float* __restrict__ Wc)
{
    __shared__ float xs[128][32];
    __shared__ float ws[32][32];

    const int row0 = blockIdx.x * 128;
    const int tid  = threadIdx.x;
    const int tx = tid & 31;
    const int ty = tid >> 5;

    float acc[16];
#pragma unroll
    for (int r = 0; r < 16; r++) acc[r] = 0.f;

    for (int k0 = 0; k0 < DINNER; k0 += 32) {
        __syncthreads();
#pragma unroll
        for (int i = 0; i < 4; i++) {
            int lin = (tid + i * 256) * 4;
            int r = lin >> 5, c = lin & 31;
            float4 v = *(const float4*)&g_xc[(size_t)(row0 + r) * DINNER + k0 + c];
            *(float4*)&xs[r][c] = v;
        }
        {
            int lin = tid * 4;
            int kk = lin >> 5, c = lin & 31;
            float4 v;
            if (c < 16) v = *(const float4*)&Wb[(size_t)(k0 + kk) * 16 + c];
            else        v = *(const float4*)&Wc[(size_t)(k0 + kk) * 16 + (c - 16)];
            *(float4*)&ws[kk][c] = v;
        }
        __syncthreads();

#pragma unroll
        for (int kk = 0; kk < 32; kk++) {
            float w = ws[kk][tx];
#pragma unroll
            for (int r = 0; r < 16; r++)
                acc[r] += xs[ty * 16 + r][kk] * w;
        }
    }

#pragma unroll
    for (int r = 0; r < 16; r++)
        g_bc[(size_t)(row0 + ty * 16 + r) * 32 + tx] = acc[r];
}

// ---------------------------------------------------------------------------
// Chunked scan: phase A (chunk end-states from 0), combine, phase C (replay).
// ---------------------------------------------------------------------------
__global__ void scan_phaseA(const float* __restrict__ A)
{
    __shared__ float bcs[CHUNK][32];
    const int b = blockIdx.x >> 5;
    const int c = blockIdx.x & 31;
    const int tid = threadIdx.x;

    const size_t base = (size_t)b * SEQ + (size_t)c * CHUNK;
    const size_t grow = (base + tid) * 32;
#pragma unroll
    for (int i = 0; i < 8; i++)
        *(float4*)&bcs[tid][i * 4] = *(const float4*)&g_bc[grow + i * 4];
    __syncthreads();

    if (tid < DSTATE) {
        float dec = 1.f / (1.f + expf(A[tid]));
        float st = 0.f;
        for (int l = 0; l < CHUNK; l++)
            st = fmaf(st, dec, bcs[l][tid]);
        g_E[(b * NCHUNK + c) * DSTATE + tid] = st;
    }
}

__global__ void scan_combine(const float* __restrict__ A)
{
    const int b = blockIdx.x;
    const int s = threadIdx.x;
    float dec  = 1.f / (1.f + expf(A[s]));
    float d128 = powf(dec, (float)CHUNK);
    float S = 0.f;
    for (int c = 0; c < NCHUNK; c++) {
        g_init[(b * NCHUNK + c) * DSTATE + s] = S;
        S = S * d128 + g_E[(b * NCHUNK + c) * DSTATE + s];
    }
}

__global__ void scan_phaseC(const float* __restrict__ A)
{
    __shared__ float bcs[CHUNK][32];
    const int b = blockIdx.x >> 5;
    const int c = blockIdx.x & 31;
    const int tid = threadIdx.x;

    const size_t base = (size_t)b * SEQ + (size_t)c * CHUNK;
    const size_t grow = (base + tid) * 32;
#pragma unroll
    for (int i = 0; i < 8; i++)
        *(float4*)&bcs[tid][i * 4] = *(const float4*)&g_bc[grow + i * 4];
    __syncthreads();

    if (tid < DSTATE) {
        float dec = 1.f / (1.f + expf(A[tid]));
        float st = g_init[(b * NCHUNK + c) * DSTATE + tid];
        for (int l = 0; l < CHUNK; l++) {
            st = fmaf(st, dec, bcs[l][tid]);
            float v = st * bcs[l][16 + tid];
#pragma unroll
            for (int m = 8; m >= 1; m >>= 1)
                v += __shfl_xor_sync(0x0000ffffu, v, m, 16);
            if (tid == 0) g_ys[base + l] = v;
        }
    }
}

// ---------------------------------------------------------------------------
// Gating elementwise, IN PLACE on g_xc: xc <- (ys + xc*D) * silu(res)
// ---------------------------------------------------------------------------
__global__ void gate_y(const float* __restrict__ Dv)
{
    size_t idx = (size_t)blockIdx.x * 256 + threadIdx.x;
    int c = (int)(idx & (DINNER - 1));
    size_t row = idx >> 11;

    float xc  = g_xc[idx];
    float ysv = g_ys[row];
    float res = g_xr[row * (size_t)(2*DINNER) + DINNER + c];
    float sr  = res / (1.f + expf(-res));
    g_xc[idx] = (ysv + xc * Dv[c]) * sr;
}

// ---------------------------------------------------------------------------
// Launch
// ---------------------------------------------------------------------------
extern "C" void kernel_launch(void* const* d_in, const int* in_sizes, int n_in,
                              void* d_out, int out_size)
{
    const float* x      = (const float*)d_in[0];
    const float* W_in   = (const float*)d_in[1];
    const float* conv_w = (const float*)d_in[2];
    const float* conv_b = (const float*)d_in[3];
    const float* W_B    = (const float*)d_in[4];
    const float* W_C    = (const float*)d_in[5];
    const float* A      = (const float*)d_in[6];
    const float* Dv     = (const float*)d_in[7];
    const float* W_out  = (const float*)d_in[8];
    float* out = (float*)d_out;

    float *xr_p, *xc_p;
    cudaGetSymbolAddress((void**)&xr_p, g_xr);
    cudaGetSymbolAddress((void**)&xc_p, g_xc);

    // 1) xr = x @ W_in  (16384 x 4096, K=1024)  [fp16 mma + ldmatrix]
    {
        dim3 grid((2*DINNER) / 128, BL / 128);
        h16gemm<<<grid, 256>>>(x, W_in, xr_p, BL, 2*DINNER, DMODEL);
    }
    // 2) depthwise conv + bias + silu -> xc
    conv_silu<<<(BL * (size_t)DINNER) / 256, 256>>>(conv_w, conv_b);
    // 3) [Bt|Ct] = xc @ [W_B|W_C]
    bc_gemm<<<BL / 128, 256>>>(W_B, W_C);
    // 4) chunked scan -> ys
    scan_phaseA<<<BATCH * NCHUNK, CHUNK>>>(A);
    scan_combine<<<BATCH, DSTATE>>>(A);
    scan_phaseC<<<BATCH * NCHUNK, CHUNK>>>(A);
    // 5) gating elementwise, in place -> g_xc now holds y
    gate_y<<<(BL * (size_t)DINNER) / 256, 256>>>(Dv);
    // 6) out = y @ W_out  (16384 x 1024, K=2048)  [fp16 mma + ldmatrix]
    {
        dim3 grid(DMODEL / 128, BL / 128);
        h16gemm<<<grid, 256>>>(xc_p, W_out, out, BL, DMODEL, DINNER);
    }
}

// round 10
// speedup vs baseline: 1.4243x; 1.2016x over previous
#include <cuda_runtime.h>
#include <cuda_fp16.h>
#include <cstddef>
#include <cstdint>

// Problem constants
#define BATCH   4
#define SEQ     4096
#define DMODEL  1024
#define DSTATE  16
#define DINNER  2048
#define BL      (BATCH*SEQ)          // 16384 rows
#define NCHUNK  32                   // SEQ/128 scan chunks
#define CHUNK   128

// ---------------------------------------------------------------------------
// Scratch (device globals; allocation APIs are forbidden)
// ---------------------------------------------------------------------------
__device__ float  g_xr[(size_t)BL * (2*DINNER)];  // x @ W_in (main | res) 256MB
__device__ float  g_xc[(size_t)BL * DINNER];      // conv+silu output      128MB
__device__ __half g_yh[(size_t)BL * DINNER];      // gated y, fp16          64MB
__device__ float  g_bc[(size_t)BL * 32];          // [Bt | Ct] per row
__device__ float  g_ys[(size_t)BL];               // scan scalar output
__device__ float  g_E   [BATCH * NCHUNK * DSTATE];
__device__ float  g_init[BATCH * NCHUNK * DSTATE];

// ===========================================================================
// FP16 tensor-core GEMM (ldmatrix + m16n8k16, fp32 accum).
// 128x128 block tile, BK=32, 256 threads (8 warps 2x4), warp tile 64x32.
// Two variants: fp32 A (converted at staging) and fp16 A (direct).
// ===========================================================================
#define HBK   32
#define ASTRH 40     // A smem row stride in halves (32 + 8 pad)
#define BSTRH 136    // B smem row stride in halves (128 + 8 pad)

__device__ __forceinline__ uint32_t pkh(float a, float b) {
    __half2 h = __floats2half2_rn(a, b);
    return reinterpret_cast<uint32_t&>(h);
}

__device__ __forceinline__ uint32_t smem_u32(const void* p) {
    uint32_t a;
    asm("{ .reg .u64 t; cvta.to.shared.u64 t, %1; cvt.u32.u64 %0, t; }"
        : "=r"(a) : "l"(p));
    return a;
}

__device__ __forceinline__ void ldsm_x4(uint32_t r[4], uint32_t addr) {
    asm volatile("ldmatrix.sync.aligned.m8n8.x4.shared.b16 {%0,%1,%2,%3}, [%4];"
        : "=r"(r[0]), "=r"(r[1]), "=r"(r[2]), "=r"(r[3]) : "r"(addr));
}
__device__ __forceinline__ void ldsm_x4t(uint32_t r[4], uint32_t addr) {
    asm volatile("ldmatrix.sync.aligned.m8n8.x4.trans.shared.b16 {%0,%1,%2,%3}, [%4];"
        : "=r"(r[0]), "=r"(r[1]), "=r"(r[2]), "=r"(r[3]) : "r"(addr));
}

__device__ __forceinline__ void mma_f16(float d[4], const uint32_t a[4], const uint32_t b0, const uint32_t b1) {
    asm volatile(
        "mma.sync.aligned.m16n8k16.row.col.f32.f16.f16.f32 "
        "{%0,%1,%2,%3}, {%4,%5,%6,%7}, {%8,%9}, {%0,%1,%2,%3};\n"
        : "+f"(d[0]), "+f"(d[1]), "+f"(d[2]), "+f"(d[3])
        : "r"(a[0]), "r"(a[1]), "r"(a[2]), "r"(a[3]), "r"(b0), "r"(b1));
}

// ---- shared mainloop body (A staging differs via functors) -----------------
__global__ __launch_bounds__(256)
void h16gemm(const float* __restrict__ A, const float* __restrict__ B,
             float* __restrict__ C, int M, int N, int K)
{
    __shared__ __align__(16) __half Asm[2][128 * ASTRH];
    __shared__ __align__(16) __half Bsm[2][HBK * BSTRH];

    const int tid  = threadIdx.x;
    const int lane = tid & 31;
    const int wid  = tid >> 5;
    const int wm   = wid >> 2;
    const int wn   = wid & 3;
    const int m0   = blockIdx.y * 128;
    const int n0   = blockIdx.x * 128;
    const int g    = lane >> 2;
    const int t    = lane & 3;
    const int grp  = lane >> 3;
    const int wi   = lane & 7;

    float acc[4][4][4];
#pragma unroll
    for (int mi = 0; mi < 4; mi++)
#pragma unroll
        for (int ni = 0; ni < 4; ni++)
#pragma unroll
            for (int r = 0; r < 4; r++) acc[mi][ni][r] = 0.f;

    const int NT = K / HBK;
    float4 ar[4], br[4];

    auto ldg = [&](int kt) {
        const float* Ag = A + (size_t)m0 * K + kt * HBK;
#pragma unroll
        for (int i = 0; i < 4; i++) {
            int idx = tid + i * 256;
            int r = idx >> 3, c4 = (idx & 7) * 4;
            ar[i] = *(const float4*)&Ag[(size_t)r * K + c4];
        }
        const float* Bg = B + (size_t)(kt * HBK) * N + n0;
#pragma unroll
        for (int i = 0; i < 4; i++) {
            int idx = tid + i * 256;
            int kr = idx >> 5, nq = (idx & 31) * 4;
            br[i] = *(const float4*)&Bg[(size_t)kr * N + nq];
        }
    };
    auto sts = [&](int buf) {
#pragma unroll
        for (int i = 0; i < 4; i++) {
            int idx = tid + i * 256;
            int r = idx >> 3, c4 = (idx & 7) * 4;
            uint2 u = make_uint2(pkh(ar[i].x, ar[i].y), pkh(ar[i].z, ar[i].w));
            *(uint2*)&Asm[buf][r * ASTRH + c4] = u;
        }
#pragma unroll
        for (int i = 0; i < 4; i++) {
            int idx = tid + i * 256;
            int kr = idx >> 5, nq = (idx & 31) * 4;
            uint2 u = make_uint2(pkh(br[i].x, br[i].y), pkh(br[i].z, br[i].w));
            *(uint2*)&Bsm[buf][kr * BSTRH + nq] = u;
        }
    };

    ldg(0); sts(0);
    __syncthreads();

    for (int kt = 0; kt < NT; kt++) {
        if (kt + 1 < NT) ldg(kt + 1);

        const uint32_t asB = smem_u32(&Asm[kt & 1][0]);
        const uint32_t bsB = smem_u32(&Bsm[kt & 1][0]);

#pragma unroll
        for (int ks = 0; ks < 2; ks++) {
            const int kh = ks * 16;
            uint32_t af[4][4], bq[2][4];
#pragma unroll
            for (int mi = 0; mi < 4; mi++) {
                int row  = wm * 64 + mi * 16 + (grp & 1) * 8 + wi;
                int colh = kh + (grp >> 1) * 8;
                ldsm_x4(af[mi], asB + (uint32_t)(row * ASTRH + colh) * 2);
            }
#pragma unroll
            for (int p = 0; p < 2; p++) {
                int krow = kh + (grp & 1) * 8 + wi;
                int ncol = wn * 32 + p * 16 + (grp >> 1) * 8;
                ldsm_x4t(bq[p], bsB + (uint32_t)(krow * BSTRH + ncol) * 2);
            }
#pragma unroll
            for (int mi = 0; mi < 4; mi++) {
                mma_f16(acc[mi][0], af[mi], bq[0][0], bq[0][1]);
                mma_f16(acc[mi][1], af[mi], bq[0][2], bq[0][3]);
                mma_f16(acc[mi][2], af[mi], bq[1][0], bq[1][1]);
                mma_f16(acc[mi][3], af[mi], bq[1][2], bq[1][3]);
            }
        }

        if (kt + 1 < NT) sts((kt + 1) & 1);
        __syncthreads();
    }

#pragma unroll
    for (int mi = 0; mi < 4; mi++) {
#pragma unroll
        for (int ni = 0; ni < 4; ni++) {
            int r = m0 + wm * 64 + mi * 16 + g;
            int c = n0 + wn * 32 + ni * 8 + t * 2;
            *(float2*)&C[(size_t)r * N + c]       = make_float2(acc[mi][ni][0], acc[mi][ni][1]);
            *(float2*)&C[(size_t)(r + 8) * N + c] = make_float2(acc[mi][ni][2], acc[mi][ni][3]);
        }
    }
}

// Variant: A already fp16 in gmem (direct uint4 LDG -> STS, no cvt on A path).
__global__ __launch_bounds__(256)
void h16gemm_hA(const __half* __restrict__ A, const float* __restrict__ B,
                float* __restrict__ C, int M, int N, int K)
{
    __shared__ __align__(16) __half Asm[2][128 * ASTRH];
    __shared__ __align__(16) __half Bsm[2][HBK * BSTRH];

    const int tid  = threadIdx.x;
    const int lane = tid & 31;
    const int wid  = tid >> 5;
    const int wm   = wid >> 2;
    const int wn   = wid & 3;
    const int m0   = blockIdx.y * 128;
    const int n0   = blockIdx.x * 128;
    const int g    = lane >> 2;
    const int t    = lane & 3;
    const int grp  = lane >> 3;
    const int wi   = lane & 7;

    float acc[4][4][4];
#pragma unroll
    for (int mi = 0; mi < 4; mi++)
#pragma unroll
        for (int ni = 0; ni < 4; ni++)
#pragma unroll
            for (int r = 0; r < 4; r++) acc[mi][ni][r] = 0.f;

    const int NT = K / HBK;
    uint4 arh[2];      // A: 128x32 halves = 512 uint4, 2 per thread
    float4 br[4];

    auto ldg = [&](int kt) {
        const __half* Ag = A + (size_t)m0 * K + kt * HBK;
#pragma unroll
        for (int i = 0; i < 2; i++) {
            int idx = tid + i * 256;          // 512 uint4 over 128 rows x 4 groups
            int r = idx >> 2, c8 = (idx & 3) * 8;
            arh[i] = *(const uint4*)&Ag[(size_t)r * K + c8];
        }
        const float* Bg = B + (size_t)(kt * HBK) * N + n0;
#pragma unroll
        for (int i = 0; i < 4; i++) {
            int idx = tid + i * 256;
            int kr = idx >> 5, nq = (idx & 31) * 4;
            br[i] = *(const float4*)&Bg[(size_t)kr * N + nq];
        }
    };
    auto sts = [&](int buf) {
#pragma unroll
        for (int i = 0; i < 2; i++) {
            int idx = tid + i * 256;
            int r = idx >> 2, c8 = (idx & 3) * 8;
            *(uint4*)&Asm[buf][r * ASTRH + c8] = arh[i];
        }
#pragma unroll
        for (int i = 0; i < 4; i++) {
            int idx = tid + i * 256;
            int kr = idx >> 5, nq = (idx & 31) * 4;
            uint2 u = make_uint2(pkh(br[i].x, br[i].y), pkh(br[i].z, br[i].w));
            *(uint2*)&Bsm[buf][kr * BSTRH + nq] = u;
        }
    };

    ldg(0); sts(0);
    __syncthreads();

    for (int kt = 0; kt < NT; kt++) {
        if (kt + 1 < NT) ldg(kt + 1);

        const uint32_t asB = smem_u32(&Asm[kt & 1][0]);
        const uint32_t bsB = smem_u32(&Bsm[kt & 1][0]);

#pragma unroll
        for (int ks = 0; ks < 2; ks++) {
            const int kh = ks * 16;
            uint32_t af[4][4], bq[2][4];
#pragma unroll
            for (int mi = 0; mi < 4; mi++) {
                int row  = wm * 64 + mi * 16 + (grp & 1) * 8 + wi;
                int colh = kh + (grp >> 1) * 8;
                ldsm_x4(af[mi], asB + (uint32_t)(row * ASTRH + colh) * 2);
            }
#pragma unroll
            for (int p = 0; p < 2; p++) {
                int krow = kh + (grp & 1) * 8 + wi;
                int ncol = wn * 32 + p * 16 + (grp >> 1) * 8;
                ldsm_x4t(bq[p], bsB + (uint32_t)(krow * BSTRH + ncol) * 2);
            }
#pragma unroll
            for (int mi = 0; mi < 4; mi++) {
                mma_f16(acc[mi][0], af[mi], bq[0][0], bq[0][1]);
                mma_f16(acc[mi][1], af[mi], bq[0][2], bq[0][3]);
                mma_f16(acc[mi][2], af[mi], bq[1][0], bq[1][1]);
                mma_f16(acc[mi][3], af[mi], bq[1][2], bq[1][3]);
            }
        }

        if (kt + 1 < NT) sts((kt + 1) & 1);
        __syncthreads();
    }

#pragma unroll
    for (int mi = 0; mi < 4; mi++) {
#pragma unroll
        for (int ni = 0; ni < 4; ni++) {
            int r = m0 + wm * 64 + mi * 16 + g;
            int c = n0 + wn * 32 + ni * 8 + t * 2;
            *(float2*)&C[(size_t)r * N + c]       = make_float2(acc[mi][ni][0], acc[mi][ni][1]);
            *(float2*)&C[(size_t)(r + 8) * N + c] = make_float2(acc[mi][ni][2], acc[mi][ni][3]);
        }
    }
}

// ---------------------------------------------------------------------------
// Depthwise conv (k=3, pad 1, along seq) + bias + SiLU, vectorized x4.
// One thread per 4 consecutive channels of one (b,l) row.
// ---------------------------------------------------------------------------
__global__ void conv_silu(const float* __restrict__ conv_w, const float* __restrict__ conv_b)
{
    size_t vidx = (size_t)blockIdx.x * 256 + threadIdx.x;  // over BL*DINNER/4
    int c4  = (int)((vidx & (DINNER/4 - 1)) << 2);         // channel base
    size_t row = vidx >> 9;                                // /(DINNER/4)
    int l = (int)(row & (SEQ - 1));

    const float* base1 = &g_xr[row * (size_t)(2*DINNER) + c4];
    float4 x1 = *(const float4*)base1;
    float4 x0 = (l > 0)       ? *(const float4*)(base1 - 2*DINNER) : make_float4(0,0,0,0);
    float4 x2 = (l < SEQ - 1) ? *(const float4*)(base1 + 2*DINNER) : make_float4(0,0,0,0);

    float4 r;
#pragma unroll
    for (int j = 0; j < 4; j++) {
        int c = c4 + j;
        float w0 = conv_w[c * 3 + 0];
        float w1 = conv_w[c * 3 + 1];
        float w2 = conv_w[c * 3 + 2];
        float a  = (&x0.x)[j] * w0 + (&x1.x)[j] * w1 + (&x2.x)[j] * w2 + conv_b[c];
        (&r.x)[j] = a / (1.f + expf(-a));
    }
    *(float4*)&g_xc[row * (size_t)DINNER + c4] = r;
}

// ---------------------------------------------------------------------------
// Skinny GEMM: [Bt|Ct] (BL x 32) = xc (BL x 2048) * [W_B | W_C]
// ---------------------------------------------------------------------------
__global__ __launch_bounds__(256, 4)
void bc_gemm(const float* __restrict__ Wb, const float* __restrict__ Wc)
{
    __shared__ float xs[128][32];
    __shared__ float ws[32][32];

    const int row0 = blockIdx.x * 128;
    const int tid  = threadIdx.x;
    const int tx = tid & 31;
    const int ty = tid >> 5;

    float acc[16];
#pragma unroll
    for (int r = 0; r < 16; r++) acc[r] = 0.f;

    for (int k0 = 0; k0 < DINNER; k0 += 32) {
        __syncthreads();
#pragma unroll
        for (int i = 0; i < 4; i++) {
            int lin = (tid + i * 256) * 4;
            int r = lin >> 5, c = lin & 31;
            float4 v = *(const float4*)&g_xc[(size_t)(row0 + r) * DINNER + k0 + c];
            *(float4*)&xs[r][c] = v;
        }
        {
            int lin = tid * 4;
            int kk = lin >> 5, c = lin & 31;
            float4 v;
            if (c < 16) v = *(const float4*)&Wb[(size_t)(k0 + kk) * 16 + c];
            else        v = *(const float4*)&Wc[(size_t)(k0 + kk) * 16 + (c - 16)];
            *(float4*)&ws[kk][c] = v;
        }
        __syncthreads();

#pragma unroll
        for (int kk = 0; kk < 32; kk++) {
            float w = ws[kk][tx];
#pragma unroll
            for (int r = 0; r < 16; r++)
                acc[r] += xs[ty * 16 + r][kk] * w;
        }
    }

#pragma unroll
    for (int r = 0; r < 16; r++)
        g_bc[(size_t)(row0 + ty * 16 + r) * 32 + tx] = acc[r];
}

// ---------------------------------------------------------------------------
// Chunked scan: phase A (chunk end-states from 0), combine, phase C (replay).
// ---------------------------------------------------------------------------
__global__ void scan_phaseA(const float* __restrict__ A)
{
    __shared__ float bcs[CHUNK][32];
    const int b = blockIdx.x >> 5;
    const int c = blockIdx.x & 31;
    const int tid = threadIdx.x;

    const size_t base = (size_t)b * SEQ + (size_t)c * CHUNK;
    const size_t grow = (base + tid) * 32;
#pragma unroll
    for (int i = 0; i < 8; i++)
        *(float4*)&bcs[tid][i * 4] = *(const float4*)&g_bc[grow + i * 4];
    __syncthreads();

    if (tid < DSTATE) {
        float dec = 1.f / (1.f + expf(A[tid]));
        float st = 0.f;
        for (int l = 0; l < CHUNK; l++)
            st = fmaf(st, dec, bcs[l][tid]);
        g_E[(b * NCHUNK + c) * DSTATE + tid] = st;
    }
}

__global__ void scan_combine(const float* __restrict__ A)
{
    const int b = blockIdx.x;
    const int s = threadIdx.x;
    float dec  = 1.f / (1.f + expf(A[s]));
    float d128 = powf(dec, (float)CHUNK);
    float S = 0.f;
    for (int c = 0; c < NCHUNK; c++) {
        g_init[(b * NCHUNK + c) * DSTATE + s] = S;
        S = S * d128 + g_E[(b * NCHUNK + c) * DSTATE + s];
    }
}

__global__ void scan_phaseC(const float* __restrict__ A)
{
    __shared__ float bcs[CHUNK][32];
    const int b = blockIdx.x >> 5;
    const int c = blockIdx.x & 31;
    const int tid = threadIdx.x;

    const size_t base = (size_t)b * SEQ + (size_t)c * CHUNK;
    const size_t grow = (base + tid) * 32;
#pragma unroll
    for (int i = 0; i < 8; i++)
        *(float4*)&bcs[tid][i * 4] = *(const float4*)&g_bc[grow + i * 4];
    __syncthreads();

    if (tid < DSTATE) {
        float dec = 1.f / (1.f + expf(A[tid]));
        float st = g_init[(b * NCHUNK + c) * DSTATE + tid];
        for (int l = 0; l < CHUNK; l++) {
            st = fmaf(st, dec, bcs[l][tid]);
            float v = st * bcs[l][16 + tid];
#pragma unroll
            for (int m = 8; m >= 1; m >>= 1)
                v += __shfl_xor_sync(0x0000ffffu, v, m, 16);
            if (tid == 0) g_ys[base + l] = v;
        }
    }
}

// ---------------------------------------------------------------------------
// Gating elementwise, vectorized x4, fp16 output:
//   yh = half((ys + xc*D) * silu(res))
// ---------------------------------------------------------------------------
__global__ void gate_y(const float* __restrict__ Dv)
{
    size_t vidx = (size_t)blockIdx.x * 256 + threadIdx.x;  // over BL*DINNER/4
    int c4  = (int)((vidx & (DINNER/4 - 1)) << 2);
    size_t row = vidx >> 9;

    float4 xc  = *(const float4*)&g_xc[row * (size_t)DINNER + c4];
    float4 res = *(const float4*)&g_xr[row * (size_t)(2*DINNER) + DINNER + c4];
    float4 dv  = *(const float4*)&Dv[c4];
    float ysv  = g_ys[row];

    float y0 = (ysv + xc.x * dv.x) * (res.x / (1.f + expf(-res.x)));
    float y1 = (ysv + xc.y * dv.y) * (res.y / (1.f + expf(-res.y)));
    float y2 = (ysv + xc.z * dv.z) * (res.z / (1.f + expf(-res.z)));
    float y3 = (ysv + xc.w * dv.w) * (res.w / (1.f + expf(-res.w)));

    uint2 u = make_uint2(pkh(y0, y1), pkh(y2, y3));
    *(uint2*)&g_yh[row * (size_t)DINNER + c4] = u;
}

// ---------------------------------------------------------------------------
// Launch
// ---------------------------------------------------------------------------
extern "C" void kernel_launch(void* const* d_in, const int* in_sizes, int n_in,
                              void* d_out, int out_size)
{
    const float* x      = (const float*)d_in[0];
    const float* W_in   = (const float*)d_in[1];
    const float* conv_w = (const float*)d_in[2];
    const float* conv_b = (const float*)d_in[3];
    const float* W_B    = (const float*)d_in[4];
    const float* W_C    = (const float*)d_in[5];
    const float* A      = (const float*)d_in[6];
    const float* Dv     = (const float*)d_in[7];
    const float* W_out  = (const float*)d_in[8];
    float* out = (float*)d_out;

    float *xr_p;
    __half *yh_p;
    cudaGetSymbolAddress((void**)&xr_p, g_xr);
    cudaGetSymbolAddress((void**)&yh_p, g_yh);

    // 1) xr = x @ W_in  (16384 x 4096, K=1024)  [fp16 mma + ldmatrix]
    {
        dim3 grid((2*DINNER) / 128, BL / 128);
        h16gemm<<<grid, 256>>>(x, W_in, xr_p, BL, 2*DINNER, DMODEL);
    }
    // 2) depthwise conv + bias + silu -> xc  (vectorized x4)
    conv_silu<<<(BL * (size_t)DINNER / 4) / 256, 256>>>(conv_w, conv_b);
    // 3) [Bt|Ct] = xc @ [W_B|W_C]
    bc_gemm<<<BL / 128, 256>>>(W_B, W_C);
    // 4) chunked scan -> ys
    scan_phaseA<<<BATCH * NCHUNK, CHUNK>>>(A);
    scan_combine<<<BATCH, DSTATE>>>(A);
    scan_phaseC<<<BATCH * NCHUNK, CHUNK>>>(A);
    // 5) gating elementwise -> g_yh (fp16)
    gate_y<<<(BL * (size_t)DINNER / 4) / 256, 256>>>(Dv);
    // 6) out = y @ W_out  (16384 x 1024, K=2048)  [fp16 A direct]
    {
        dim3 grid(DMODEL / 128, BL / 128);
        h16gemm_hA<<<grid, 256>>>(yh_p, W_out, out, BL, DMODEL, DINNER);
    }
}

// round 11
// speedup vs baseline: 1.9228x; 1.3500x over previous
#include <cuda_runtime.h>
#include <cuda_fp16.h>
#include <cstddef>
#include <cstdint>

// Problem constants
#define BATCH   4
#define SEQ     4096
#define DMODEL  1024
#define DSTATE  16
#define DINNER  2048
#define BL      (BATCH*SEQ)          // 16384 rows
#define NCHUNK  32                   // SEQ/128 scan chunks
#define CHUNK   128

// ---------------------------------------------------------------------------
// Scratch (device globals; allocation APIs are forbidden)
// ---------------------------------------------------------------------------
__device__ __half g_xh  [(size_t)BL * DMODEL];      // x in fp16          32MB
__device__ __half g_Winh[(size_t)DMODEL * 2*DINNER];// W_in fp16           8MB
__device__ __half g_Wouth[(size_t)DINNER * DMODEL]; // W_out fp16          4MB
__device__ __half g_xrh [(size_t)BL * (2*DINNER)];  // xr fp16 (main|res) 128MB
__device__ __half g_xch [(size_t)BL * DINNER];      // conv+silu fp16     64MB
__device__ __half g_yh  [(size_t)BL * DINNER];      // gated y fp16       64MB
__device__ float  g_bc[(size_t)BL * 32];            // [Bt | Ct]
__device__ float  g_ys[(size_t)BL];
__device__ float  g_E   [BATCH * NCHUNK * DSTATE];
__device__ float  g_init[BATCH * NCHUNK * DSTATE];

// ===========================================================================
// helpers
// ===========================================================================
#define HBK   32
#define ASTRH 40     // A smem row stride in halves (32 + 8 pad)
#define BSTRH 136    // B smem row stride in halves (128 + 8 pad)
#define A_STAGE (128 * ASTRH)            // halves
#define B_STAGE (HBK * BSTRH)            // halves
#define GEMM_SMEM_BYTES ((3 * (A_STAGE + B_STAGE)) * 2)

__device__ __forceinline__ uint32_t pkh(float a, float b) {
    __half2 h = __floats2half2_rn(a, b);
    return reinterpret_cast<uint32_t&>(h);
}

__device__ __forceinline__ uint32_t smem_u32(const void* p) {
    uint32_t a;
    asm("{ .reg .u64 t; cvta.to.shared.u64 t, %1; cvt.u32.u64 %0, t; }"
        : "=r"(a) : "l"(p));
    return a;
}

__device__ __forceinline__ void cpa16(uint32_t dst_smem, const void* src_gmem) {
    asm volatile("cp.async.cg.shared.global [%0], [%1], 16;"
                 :: "r"(dst_smem), "l"(src_gmem));
}

__device__ __forceinline__ void ldsm_x4(uint32_t r[4], uint32_t addr) {
    asm volatile("ldmatrix.sync.aligned.m8n8.x4.shared.b16 {%0,%1,%2,%3}, [%4];"
        : "=r"(r[0]), "=r"(r[1]), "=r"(r[2]), "=r"(r[3]) : "r"(addr));
}
__device__ __forceinline__ void ldsm_x4t(uint32_t r[4], uint32_t addr) {
    asm volatile("ldmatrix.sync.aligned.m8n8.x4.trans.shared.b16 {%0,%1,%2,%3}, [%4];"
        : "=r"(r[0]), "=r"(r[1]), "=r"(r[2]), "=r"(r[3]) : "r"(addr));
}

__device__ __forceinline__ void mma_f16(float d[4], const uint32_t a[4], const uint32_t b0, const uint32_t b1) {
    asm volatile(
        "mma.sync.aligned.m16n8k16.row.col.f32.f16.f16.f32 "
        "{%0,%1,%2,%3}, {%4,%5,%6,%7}, {%8,%9}, {%0,%1,%2,%3};\n"
        : "+f"(d[0]), "+f"(d[1]), "+f"(d[2]), "+f"(d[3])
        : "r"(a[0]), "r"(a[1]), "r"(a[2]), "r"(a[3]), "r"(b0), "r"(b1));
}

// ===========================================================================
// fp32 -> fp16 elementwise convert (8 elems/thread)
// ===========================================================================
__global__ void cvt_f32_f16(const float* __restrict__ src, __half* __restrict__ dst)
{
    size_t i8 = ((size_t)blockIdx.x * 256 + threadIdx.x) * 8;
    float4 a = *(const float4*)&src[i8];
    float4 b = *(const float4*)&src[i8 + 4];
    uint4 u = make_uint4(pkh(a.x, a.y), pkh(a.z, a.w), pkh(b.x, b.y), pkh(b.z, b.w));
    *(uint4*)&dst[i8] = u;
}

// ===========================================================================
// All-fp16-operand GEMM: C[M,N] = A[M,K]*B[K,N], A,B fp16 row-major,
// fp32 accumulate. 128x128 tile, BK=32, 256 threads, warp tile 64x32,
// 3-stage cp.async pipeline + ldmatrix + m16n8k16.
// OUTH: write C as fp16 (packed) else fp32.
// ===========================================================================
template <bool OUTH>
__global__ __launch_bounds__(256)
void h16gemm_hh(const __half* __restrict__ A, const __half* __restrict__ B,
                void* __restrict__ Cv, int M, int N, int K)
{
    extern __shared__ char raw[];
    __half* smA = (__half*)raw;                       // 3 stages of A
    __half* smB = (__half*)raw + 3 * A_STAGE;         // 3 stages of B
    const uint32_t smA0 = smem_u32(smA);
    const uint32_t smB0 = smem_u32(smB);

    const int tid  = threadIdx.x;
    const int lane = tid & 31;
    const int wid  = tid >> 5;
    const int wm   = wid >> 2;
    const int wn   = wid & 3;
    const int m0   = blockIdx.y * 128;
    const int n0   = blockIdx.x * 128;
    const int g    = lane >> 2;
    const int t    = lane & 3;
    const int grp  = lane >> 3;
    const int wi   = lane & 7;

    float acc[4][4][4];
#pragma unroll
    for (int mi = 0; mi < 4; mi++)
#pragma unroll
        for (int ni = 0; ni < 4; ni++)
#pragma unroll
            for (int r = 0; r < 4; r++) acc[mi][ni][r] = 0.f;

    const int NT = K / HBK;

    auto issue = [&](int kt) {
        const int s = kt % 3;
        const uint32_t aB = smA0 + s * A_STAGE * 2;
        const __half* Ag = A + (size_t)m0 * K + kt * HBK;
#pragma unroll
        for (int i = 0; i < 2; i++) {
            int idx = tid + i * 256;            // 512 chunks over 128 rows x 4
            int r = idx >> 2, c8 = (idx & 3) * 8;
            cpa16(aB + (uint32_t)(r * ASTRH + c8) * 2, Ag + (size_t)r * K + c8);
        }
        const uint32_t bB = smB0 + s * B_STAGE * 2;
        const __half* Bg = B + (size_t)(kt * HBK) * N + n0;
#pragma unroll
        for (int i = 0; i < 2; i++) {
            int idx = tid + i * 256;            // 512 chunks over 32 rows x 16
            int kr = idx >> 4, c8 = (idx & 15) * 8;
            cpa16(bB + (uint32_t)(kr * BSTRH + c8) * 2, Bg + (size_t)kr * N + c8);
        }
        asm volatile("cp.async.commit_group;");
    };

    issue(0);
    if (NT > 1) issue(1);

    for (int kt = 0; kt < NT; kt++) {
        if (kt + 1 < NT) asm volatile("cp.async.wait_group 1;");
        else             asm volatile("cp.async.wait_group 0;");
        __syncthreads();
        if (kt + 2 < NT) issue(kt + 2);

        const int s = kt % 3;
        const uint32_t asB = smA0 + s * A_STAGE * 2;
        const uint32_t bsB = smB0 + s * B_STAGE * 2;

#pragma unroll
        for (int ks = 0; ks < 2; ks++) {
            const int kh = ks * 16;
            uint32_t af[4][4], bq[2][4];
#pragma unroll
            for (int mi = 0; mi < 4; mi++) {
                int row  = wm * 64 + mi * 16 + (grp & 1) * 8 + wi;
                int colh = kh + (grp >> 1) * 8;
                ldsm_x4(af[mi], asB + (uint32_t)(row * ASTRH + colh) * 2);
            }
#pragma unroll
            for (int p = 0; p < 2; p++) {
                int krow = kh + (grp & 1) * 8 + wi;
                int ncol = wn * 32 + p * 16 + (grp >> 1) * 8;
                ldsm_x4t(bq[p], bsB + (uint32_t)(krow * BSTRH + ncol) * 2);
            }
#pragma unroll
            for (int mi = 0; mi < 4; mi++) {
                mma_f16(acc[mi][0], af[mi], bq[0][0], bq[0][1]);
                mma_f16(acc[mi][1], af[mi], bq[0][2], bq[0][3]);
                mma_f16(acc[mi][2], af[mi], bq[1][0], bq[1][1]);
                mma_f16(acc[mi][3], af[mi], bq[1][2], bq[1][3]);
            }
        }
    }

    // Epilogue: thread owns (g, 2t),(g,2t+1) and (g+8, ...) per 16x8 frag
#pragma unroll
    for (int mi = 0; mi < 4; mi++) {
#pragma unroll
        for (int ni = 0; ni < 4; ni++) {
            int r = m0 + wm * 64 + mi * 16 + g;
            int c = n0 + wn * 32 + ni * 8 + t * 2;
            if (OUTH) {
                __half* Ch = (__half*)Cv;
                *(uint32_t*)&Ch[(size_t)r * N + c]       = pkh(acc[mi][ni][0], acc[mi][ni][1]);
                *(uint32_t*)&Ch[(size_t)(r + 8) * N + c] = pkh(acc[mi][ni][2], acc[mi][ni][3]);
            } else {
                float* Cf = (float*)Cv;
                *(float2*)&Cf[(size_t)r * N + c]       = make_float2(acc[mi][ni][0], acc[mi][ni][1]);
                *(float2*)&Cf[(size_t)(r + 8) * N + c] = make_float2(acc[mi][ni][2], acc[mi][ni][3]);
            }
        }
    }
}

// ---------------------------------------------------------------------------
// Depthwise conv (k=3, pad 1, seq dim) + bias + SiLU; fp16 in/out, fp32 math.
// One thread per 8 consecutive channels of one (b,l) row.
// ---------------------------------------------------------------------------
__global__ void conv_silu(const float* __restrict__ conv_w, const float* __restrict__ conv_b)
{
    size_t vidx = (size_t)blockIdx.x * 256 + threadIdx.x;  // over BL*DINNER/8
    int c8  = (int)((vidx & (DINNER/8 - 1)) << 3);
    size_t row = vidx >> 8;                                // /(DINNER/8)
    int l = (int)(row & (SEQ - 1));

    const __half* base1 = &g_xrh[row * (size_t)(2*DINNER) + c8];
    uint4 u1 = *(const uint4*)base1;
    uint4 u0 = (l > 0)       ? *(const uint4*)(base1 - 2*DINNER) : make_uint4(0,0,0,0);
    uint4 u2 = (l < SEQ - 1) ? *(const uint4*)(base1 + 2*DINNER) : make_uint4(0,0,0,0);

    const __half2* h0 = (const __half2*)&u0;
    const __half2* h1 = (const __half2*)&u1;
    const __half2* h2 = (const __half2*)&u2;

    uint4 out;
    uint32_t* op = (uint32_t*)&out;
#pragma unroll
    for (int p = 0; p < 4; p++) {          // pairs of channels
        float2 f0 = __half22float2(h0[p]);
        float2 f1 = __half22float2(h1[p]);
        float2 f2 = __half22float2(h2[p]);
        int c = c8 + p * 2;
        float a0 = f0.x * conv_w[c*3+0] + f1.x * conv_w[c*3+1] + f2.x * conv_w[c*3+2] + conv_b[c];
        float a1 = f0.y * conv_w[(c+1)*3+0] + f1.y * conv_w[(c+1)*3+1] + f2.y * conv_w[(c+1)*3+2] + conv_b[c+1];
        float s0 = a0 / (1.f + expf(-a0));
        float s1 = a1 / (1.f + expf(-a1));
        op[p] = pkh(s0, s1);
    }
    *(uint4*)&g_xch[row * (size_t)DINNER + c8] = out;
}

// ---------------------------------------------------------------------------
// Skinny GEMM: [Bt|Ct] (BL x 32) = xc(fp16) (BL x 2048) * [W_B | W_C](fp32)
// ---------------------------------------------------------------------------
__global__ __launch_bounds__(256, 4)
void bc_gemm(const float* __restrict__ Wb, const float* __restrict__ Wc)
{
    __shared__ float xs[128][32];
    __shared__ float ws[32][32];

    const int row0 = blockIdx.x * 128;
    const int tid  = threadIdx.x;
    const int tx = tid & 31;
    const int ty = tid >> 5;

    float acc[16];
#pragma unroll
    for (int r = 0; r < 16; r++) acc[r] = 0.f;

    for (int k0 = 0; k0 < DINNER; k0 += 32) {
        __syncthreads();
#pragma unroll
        for (int i = 0; i < 2; i++) {
            int lin = tid + i * 256;           // 512 uint4 over 128 rows x 4
            int r = lin >> 2, c8 = (lin & 3) * 8;
            uint4 u = *(const uint4*)&g_xch[(size_t)(row0 + r) * DINNER + k0 + c8];
            const __half2* hp = (const __half2*)&u;
#pragma unroll
            for (int p = 0; p < 4; p++) {
                float2 f = __half22float2(hp[p]);
                xs[r][c8 + 2*p]     = f.x;
                xs[r][c8 + 2*p + 1] = f.y;
            }
        }
        {
            int lin = tid * 4;
            int kk = lin >> 5, c = lin & 31;
            float4 v;
            if (c < 16) v = *(const float4*)&Wb[(size_t)(k0 + kk) * 16 + c];
            else        v = *(const float4*)&Wc[(size_t)(k0 + kk) * 16 + (c - 16)];
            *(float4*)&ws[kk][c] = v;
        }
        __syncthreads();

#pragma unroll
        for (int kk = 0; kk < 32; kk++) {
            float w = ws[kk][tx];
#pragma unroll
            for (int r = 0; r < 16; r++)
                acc[r] += xs[ty * 16 + r][kk] * w;
        }
    }

#pragma unroll
    for (int r = 0; r < 16; r++)
        g_bc[(size_t)(row0 + ty * 16 + r) * 32 + tx] = acc[r];
}

// ---------------------------------------------------------------------------
// Chunked scan: phase A (chunk end-states from 0), combine, phase C (replay).
// ---------------------------------------------------------------------------
__global__ void scan_phaseA(const float* __restrict__ A)
{
    __shared__ float bcs[CHUNK][32];
    const int b = blockIdx.x >> 5;
    const int c = blockIdx.x & 31;
    const int tid = threadIdx.x;

    const size_t base = (size_t)b * SEQ + (size_t)c * CHUNK;
    const size_t grow = (base + tid) * 32;
#pragma unroll
    for (int i = 0; i < 8; i++)
        *(float4*)&bcs[tid][i * 4] = *(const float4*)&g_bc[grow + i * 4];
    __syncthreads();

    if (tid < DSTATE) {
        float dec = 1.f / (1.f + expf(A[tid]));
        float st = 0.f;
        for (int l = 0; l < CHUNK; l++)
            st = fmaf(st, dec, bcs[l][tid]);
        g_E[(b * NCHUNK + c) * DSTATE + tid] = st;
    }
}

__global__ void scan_combine(const float* __restrict__ A)
{
    const int b = blockIdx.x;
    const int s = threadIdx.x;
    float dec  = 1.f / (1.f + expf(A[s]));
    float d128 = powf(dec, (float)CHUNK);
    float S = 0.f;
    for (int c = 0; c < NCHUNK; c++) {
        g_init[(b * NCHUNK + c) * DSTATE + s] = S;
        S = S * d128 + g_E[(b * NCHUNK + c) * DSTATE + s];
    }
}

__global__ void scan_phaseC(const float* __restrict__ A)
{
    __shared__ float bcs[CHUNK][32];
    const int b = blockIdx.x >> 5;
    const int c = blockIdx.x & 31;
    const int tid = threadIdx.x;

    const size_t base = (size_t)b * SEQ + (size_t)c * CHUNK;
    const size_t grow = (base + tid) * 32;
#pragma unroll
    for (int i = 0; i < 8; i++)
        *(float4*)&bcs[tid][i * 4] = *(const float4*)&g_bc[grow + i * 4];
    __syncthreads();

    if (tid < DSTATE) {
        float dec = 1.f / (1.f + expf(A[tid]));
        float st = g_init[(b * NCHUNK + c) * DSTATE + tid];
        for (int l = 0; l < CHUNK; l++) {
            st = fmaf(st, dec, bcs[l][tid]);
            float v = st * bcs[l][16 + tid];
#pragma unroll
            for (int m = 8; m >= 1; m >>= 1)
                v += __shfl_xor_sync(0x0000ffffu, v, m, 16);
            if (tid == 0) g_ys[base + l] = v;
        }
    }
}

// ---------------------------------------------------------------------------
// Gating elementwise (fp16 in/out): yh = half((ys + xc*D) * silu(res))
// ---------------------------------------------------------------------------
__global__ void gate_y(const float* __restrict__ Dv)
{
    size_t vidx = (size_t)blockIdx.x * 256 + threadIdx.x;  // over BL*DINNER/8
    int c8  = (int)((vidx & (DINNER/8 - 1)) << 3);
    size_t row = vidx >> 8;

    uint4 uxc  = *(const uint4*)&g_xch[row * (size_t)DINNER + c8];
    uint4 ures = *(const uint4*)&g_xrh[row * (size_t)(2*DINNER) + DINNER + c8];
    const __half2* hxc  = (const __half2*)&uxc;
    const __half2* hres = (const __half2*)&ures;
    float ysv = g_ys[row];

    uint4 out;
    uint32_t* op = (uint32_t*)&out;
#pragma unroll
    for (int p = 0; p < 4; p++) {
        float2 xc  = __half22float2(hxc[p]);
        float2 res = __half22float2(hres[p]);
        int c = c8 + p * 2;
        float y0 = (ysv + xc.x * Dv[c])     * (res.x / (1.f + expf(-res.x)));
        float y1 = (ysv + xc.y * Dv[c + 1]) * (res.y / (1.f + expf(-res.y)));
        op[p] = pkh(y0, y1);
    }
    *(uint4*)&g_yh[row * (size_t)DINNER + c8] = out;
}

// ---------------------------------------------------------------------------
// Launch
// ---------------------------------------------------------------------------
extern "C" void kernel_launch(void* const* d_in, const int* in_sizes, int n_in,
                              void* d_out, int out_size)
{
    const float* x      = (const float*)d_in[0];
    const float* W_in   = (const float*)d_in[1];
    const float* conv_w = (const float*)d_in[2];
    const float* conv_b = (const float*)d_in[3];
    const float* W_B    = (const float*)d_in[4];
    const float* W_C    = (const float*)d_in[5];
    const float* A      = (const float*)d_in[6];
    const float* Dv     = (const float*)d_in[7];
    const float* W_out  = (const float*)d_in[8];
    float* out = (float*)d_out;

    __half *xh_p, *winh_p, *wouth_p, *xrh_p, *yh_p;
    cudaGetSymbolAddress((void**)&xh_p,   g_xh);
    cudaGetSymbolAddress((void**)&winh_p, g_Winh);
    cudaGetSymbolAddress((void**)&wouth_p,g_Wouth);
    cudaGetSymbolAddress((void**)&xrh_p,  g_xrh);
    cudaGetSymbolAddress((void**)&yh_p,   g_yh);

    cudaFuncSetAttribute(h16gemm_hh<true>,  cudaFuncAttributeMaxDynamicSharedMemorySize, GEMM_SMEM_BYTES);
    cudaFuncSetAttribute(h16gemm_hh<false>, cudaFuncAttributeMaxDynamicSharedMemorySize, GEMM_SMEM_BYTES);

    // 0) fp32 -> fp16 conversions (x, W_in, W_out)
    cvt_f32_f16<<<((size_t)BL * DMODEL / 8) / 256, 256>>>(x, xh_p);
    cvt_f32_f16<<<((size_t)DMODEL * 2*DINNER / 8) / 256, 256>>>(W_in, winh_p);
    cvt_f32_f16<<<((size_t)DINNER * DMODEL / 8) / 256, 256>>>(W_out, wouth_p);

    // 1) xr(fp16) = x @ W_in   [all-fp16 operands, fp16 out]
    {
        dim3 grid((2*DINNER) / 128, BL / 128);
        h16gemm_hh<true><<<grid, 256, GEMM_SMEM_BYTES>>>(xh_p, winh_p, xrh_p, BL, 2*DINNER, DMODEL);
    }
    // 2) depthwise conv + bias + silu -> xc (fp16)
    conv_silu<<<((size_t)BL * DINNER / 8) / 256, 256>>>(conv_w, conv_b);
    // 3) [Bt|Ct] = xc @ [W_B|W_C]
    bc_gemm<<<BL / 128, 256>>>(W_B, W_C);
    // 4) chunked scan -> ys
    scan_phaseA<<<BATCH * NCHUNK, CHUNK>>>(A);
    scan_combine<<<BATCH, DSTATE>>>(A);
    scan_phaseC<<<BATCH * NCHUNK, CHUNK>>>(A);
    // 5) gating -> yh (fp16)
    gate_y<<<((size_t)BL * DINNER / 8) / 256, 256>>>(Dv);
    // 6) out(fp32) = yh @ W_out  [all-fp16 operands]
    {
        dim3 grid(DMODEL / 128, BL / 128);
        h16gemm_hh<false><<<grid, 256, GEMM_SMEM_BYTES>>>(yh_p, wouth_p, out, BL, DMODEL, DINNER);
    }
}